// round 5
// baseline (speedup 1.0000x reference)
#include <cuda_runtime.h>

// LocalActivationUnit: score[b,t] = relu([q,k,q-k,q*k] @ W0 + b0) @ W1 + b1
// Folded:  h = qA_b + k . C_b   where
//   qA_b[h] = b0[h] + sum_e q[e]*(W0[e,h] + W0[256+e,h])
//   C_b[e,h] = (W0[128+e,h] - W0[256+e,h]) + q[e]*W0[384+e,h]
// Then score = relu(h) @ W1 + b1.
//
// One CTA per batch. C_b lives in smem (32KB). Keys streamed in 64-row chunks.
// Inner matvec batched as [64 x 64] GEMM with K=128, f32x2 packed FMAs.

#define NB 1024
#define NT 200
#define NE 128
#define NH 64

#define APAD 132  // padded row stride for keys chunk in smem (floats)

__device__ __forceinline__ unsigned long long pack2(float x) {
    unsigned long long r;
    asm("mov.b64 %0, {%1, %1};" : "=l"(r) : "r"(__float_as_uint(x)));
    return r;
}
__device__ __forceinline__ void ffma2(unsigned long long &acc, unsigned long long a,
                                      unsigned long long b) {
    asm("fma.rn.f32x2 %0, %1, %2, %0;" : "+l"(acc) : "l"(a), "l"(b));
}
__device__ __forceinline__ float2 unpack2(unsigned long long v) {
    unsigned int lo, hi;
    asm("mov.b64 {%0, %1}, %2;" : "=r"(lo), "=r"(hi) : "l"(v));
    return make_float2(__uint_as_float(lo), __uint_as_float(hi));
}

__global__ void __launch_bounds__(256, 1)
lau_kernel(const float* __restrict__ query,
           const float* __restrict__ keys,
           const float* __restrict__ W0,
           const float* __restrict__ b0,
           const float* __restrict__ W1,
           const float* __restrict__ b1,
           float* __restrict__ out)
{
    extern __shared__ float smem[];
    float* sC  = smem;                    // [128][64]  = 8192 floats
    float* sA  = smem + NE * NH;          // [64][APAD] = 8448 floats (also scratch)
    float* sq  = sA + 64 * APAD;          // [128]
    float* sqA = sq + NE;                 // [64]

    const int tid = threadIdx.x;
    const int b   = blockIdx.x;

    // ---- load q ----
    if (tid < NE) sq[tid] = query[b * NE + tid];
    __syncthreads();

    // ---- precompute C_b into smem + qA partials ----
    const float* W0b = W0 + 128 * NH;
    const float* W0c = W0 + 256 * NH;
    const float* W0d = W0 + 384 * NH;
    #pragma unroll
    for (int j = 0; j < 8; j++) {
        int f = tid + 256 * j;          // float4 index, [0, 2048)
        int e = f >> 4;                 // 16 float4 per e-row
        float qe = sq[e];
        float4 wb = *(const float4*)(W0b + f * 4);
        float4 wc = *(const float4*)(W0c + f * 4);
        float4 wd = *(const float4*)(W0d + f * 4);
        float4 c;
        c.x = (wb.x - wc.x) + qe * wd.x;
        c.y = (wb.y - wc.y) + qe * wd.y;
        c.z = (wb.z - wc.z) + qe * wd.z;
        c.w = (wb.w - wc.w) + qe * wd.w;
        *(float4*)&sC[f * 4] = c;
    }
    // qA partials: 4 groups of 32 e-terms each, scratch in sA
    {
        int h = tid & 63, g = tid >> 6;
        float p = 0.f;
        int e0 = g * 32;
        #pragma unroll 4
        for (int e = e0; e < e0 + 32; e++)
            p += sq[e] * (W0[e * NH + h] + W0c[e * NH + h]);
        sA[g * 64 + h] = p;
    }
    __syncthreads();
    if (tid < NH)
        sqA[tid] = b0[tid] + sA[tid] + sA[64 + tid] + sA[128 + tid] + sA[192 + tid];
    // (loop-start __syncthreads orders this vs. sA reuse)

    // ---- per-thread constants ----
    const int ty = tid >> 3;            // 0..31 -> 2 rows each (64-row chunk)
    const int tx = tid & 7;             // 0..7  -> 8 cols each
    float w1v[8];
    *(float4*)&w1v[0] = *(const float4*)(W1 + tx * 8);
    *(float4*)&w1v[4] = *(const float4*)(W1 + tx * 8 + 4);
    const float b1v = b1[0];

    const float* bp = sC + tx * 8;

    // ---- main loop over T in 64-row chunks ----
    for (int t0 = 0; t0 < NT; t0 += 64) {
        const int rows = min(64, NT - t0);
        __syncthreads();   // previous GEMM done reading sA

        // load keys chunk -> sA [rows][APAD]
        const int nf4 = rows * 32;   // 32 float4 per row
        for (int f = tid; f < nf4; f += 256) {
            int row = f >> 5, c4 = f & 31;
            float4 v = *(const float4*)(keys + ((long)b * NT + t0 + row) * NE + c4 * 4);
            *(float4*)&sA[row * APAD + c4 * 4] = v;
        }
        __syncthreads();

        // GEMM: acc[2 rows][4 col-pairs], K=128
        unsigned long long acc[2][4];
        #pragma unroll
        for (int r = 0; r < 2; r++)
            #pragma unroll
            for (int c = 0; c < 4; c++) acc[r][c] = 0ull;

        const float* a0p = sA + (ty * 2) * APAD;
        const float* a1p = a0p + APAD;
        #pragma unroll 8
        for (int e = 0; e < NE; e++) {
            unsigned long long aa0 = pack2(a0p[e]);
            unsigned long long aa1 = pack2(a1p[e]);
            ulonglong2 b01 = *(const ulonglong2*)(bp + e * NH);
            ulonglong2 b23 = *(const ulonglong2*)(bp + e * NH + 4);
            ffma2(acc[0][0], aa0, b01.x);
            ffma2(acc[0][1], aa0, b01.y);
            ffma2(acc[0][2], aa0, b23.x);
            ffma2(acc[0][3], aa0, b23.y);
            ffma2(acc[1][0], aa1, b01.x);
            ffma2(acc[1][1], aa1, b01.y);
            ffma2(acc[1][2], aa1, b23.x);
            ffma2(acc[1][3], aa1, b23.y);
        }

        // epilogue: relu(acc + qA) . W1, reduce over the 8 tx lanes
        #pragma unroll
        for (int r = 0; r < 2; r++) {
            const int trow = ty * 2 + r;
            float s = 0.f;
            #pragma unroll
            for (int cp = 0; cp < 4; cp++) {
                float2 v = unpack2(acc[r][cp]);
                int h = tx * 8 + cp * 2;
                float x0 = v.x + sqA[h];
                float x1 = v.y + sqA[h + 1];
                x0 = x0 > 0.f ? x0 : 0.f;
                x1 = x1 > 0.f ? x1 : 0.f;
                s += x0 * w1v[cp * 2] + x1 * w1v[cp * 2 + 1];
            }
            s += __shfl_down_sync(0xffffffffu, s, 4);
            s += __shfl_down_sync(0xffffffffu, s, 2);
            s += __shfl_down_sync(0xffffffffu, s, 1);
            if (tx == 0 && trow < rows)
                out[b * NT + t0 + trow] = s + b1v;
        }
    }
}

extern "C" void kernel_launch(void* const* d_in, const int* in_sizes, int n_in,
                              void* d_out, int out_size)
{
    const float* query = (const float*)d_in[0];
    const float* keys  = (const float*)d_in[1];
    const float* W0    = (const float*)d_in[2];
    const float* b0    = (const float*)d_in[3];
    const float* W1    = (const float*)d_in[4];
    const float* b1    = (const float*)d_in[5];
    float* out = (float*)d_out;

    const int smem_bytes = (NE * NH + 64 * APAD + NE + NH) * (int)sizeof(float);
    cudaFuncSetAttribute(lau_kernel, cudaFuncAttributeMaxDynamicSharedMemorySize,
                         smem_bytes);
    lau_kernel<<<NB, 256, smem_bytes>>>(query, keys, W0, b0, W1, b1, out);
}

// round 7
// speedup vs baseline: 1.9540x; 1.9540x over previous
#include <cuda_runtime.h>

// LocalActivationUnit: score[b,t] = relu([q,k,q-k,q*k] @ W0 + b0) @ W1 + b1
// Folded:  h = qA_b + k . C_b   where
//   qA_b[h] = b0[h] + sum_e q[e]*(W0[e,h] + W0[256+e,h])
//   C_b[e,h] = (W0[128+e,h] - W0[256+e,h]) + q[e]*W0[384+e,h]
// Then score = relu(h) @ W1 + b1.
//
// R5 changes vs R0:
//  - conflict-free B fragment: cols {tx*4..+3, 32+tx*4..+3} -> LDS.128 spans banks 0..31
//  - A loaded as float4 (4 e-steps amortized)
//  - 2 CTAs/SM (launch_bounds(256,2))
//  - tail chunk (rows=8): inactive warps skip the GEMM entirely

#define NB 1024
#define NT 200
#define NE 128
#define NH 64

#define APAD 132  // padded row stride for keys chunk in smem (floats), %4==0

__device__ __forceinline__ unsigned long long pack2(float x) {
    unsigned long long r;
    asm("mov.b64 %0, {%1, %1};" : "=l"(r) : "r"(__float_as_uint(x)));
    return r;
}
__device__ __forceinline__ void ffma2(unsigned long long &acc, unsigned long long a,
                                      unsigned long long b) {
    asm("fma.rn.f32x2 %0, %1, %2, %0;" : "+l"(acc) : "l"(a), "l"(b));
}
__device__ __forceinline__ float2 unpack2(unsigned long long v) {
    unsigned int lo, hi;
    asm("mov.b64 {%0, %1}, %2;" : "=r"(lo), "=r"(hi) : "l"(v));
    return make_float2(__uint_as_float(lo), __uint_as_float(hi));
}

__global__ void __launch_bounds__(256, 2)
lau_kernel(const float* __restrict__ query,
           const float* __restrict__ keys,
           const float* __restrict__ W0,
           const float* __restrict__ b0,
           const float* __restrict__ W1,
           const float* __restrict__ b1,
           float* __restrict__ out)
{
    extern __shared__ float smem[];
    float* sC  = smem;                    // [128][64]  = 8192 floats
    float* sA  = smem + NE * NH;          // [64][APAD] = 8448 floats (also scratch)
    float* sq  = sA + 64 * APAD;          // [128]
    float* sqA = sq + NE;                 // [64]

    const int tid = threadIdx.x;
    const int b   = blockIdx.x;

    // ---- load q ----
    if (tid < NE) sq[tid] = query[b * NE + tid];
    __syncthreads();

    // ---- precompute C_b into smem + qA partials ----
    const float* W0b = W0 + 128 * NH;
    const float* W0c = W0 + 256 * NH;
    const float* W0d = W0 + 384 * NH;
    #pragma unroll
    for (int j = 0; j < 8; j++) {
        int f = tid + 256 * j;          // float4 index, [0, 2048)
        int e = f >> 4;                 // 16 float4 per e-row
        float qe = sq[e];
        float4 wb = *(const float4*)(W0b + f * 4);
        float4 wc = *(const float4*)(W0c + f * 4);
        float4 wd = *(const float4*)(W0d + f * 4);
        float4 c;
        c.x = (wb.x - wc.x) + qe * wd.x;
        c.y = (wb.y - wc.y) + qe * wd.y;
        c.z = (wb.z - wc.z) + qe * wd.z;
        c.w = (wb.w - wc.w) + qe * wd.w;
        *(float4*)&sC[f * 4] = c;
    }
    // qA partials: 4 groups of 32 e-terms each, scratch in sA
    {
        int h = tid & 63, g = tid >> 6;
        float p = 0.f;
        int e0 = g * 32;
        #pragma unroll 4
        for (int e = e0; e < e0 + 32; e++)
            p += sq[e] * (W0[e * NH + h] + W0c[e * NH + h]);
        sA[g * 64 + h] = p;
    }
    __syncthreads();
    if (tid < NH)
        sqA[tid] = b0[tid] + sA[tid] + sA[64 + tid] + sA[128 + tid] + sA[192 + tid];
    // (loop-start __syncthreads orders this vs. sA reuse)

    // ---- per-thread constants ----
    const int ty = tid >> 3;            // 0..31 -> 2 rows each (64-row chunk)
    const int tx = tid & 7;             // 0..7  -> cols {tx*4..+3, 32+tx*4..+3}
    float w1v[8];
    *(float4*)&w1v[0] = *(const float4*)(W1 + tx * 4);
    *(float4*)&w1v[4] = *(const float4*)(W1 + 32 + tx * 4);
    const float b1v = b1[0];

    const float* bp = sC + tx * 4;

    // ---- main loop over T in 64-row chunks ----
    for (int t0 = 0; t0 < NT; t0 += 64) {
        const int rows = min(64, NT - t0);
        __syncthreads();   // previous GEMM done reading sA

        // load keys chunk -> sA [rows][APAD]
        const int nf4 = rows * 32;   // 32 float4 per row
        for (int f = tid; f < nf4; f += 256) {
            int row = f >> 5, c4 = f & 31;
            float4 v = *(const float4*)(keys + ((long)b * NT + t0 + row) * NE + c4 * 4);
            *(float4*)&sA[row * APAD + c4 * 4] = v;
        }
        __syncthreads();

        // tail chunk: warps whose rows are all out of range skip everything
        // (rows=8 -> only ty 0..3 = warp 0 active; condition is warp-uniform)
        if (ty * 2 >= rows) continue;

        // GEMM: acc[2 rows][4 col-pairs], K=128
        unsigned long long acc[2][4];
        #pragma unroll
        for (int r = 0; r < 2; r++)
            #pragma unroll
            for (int c = 0; c < 4; c++) acc[r][c] = 0ull;

        const float4* a0p = (const float4*)(sA + (ty * 2) * APAD);
        const float4* a1p = (const float4*)(sA + (ty * 2 + 1) * APAD);
        #pragma unroll 4
        for (int e4 = 0; e4 < NE / 4; e4++) {
            float av0[4], av1[4];
            *(float4*)av0 = a0p[e4];
            *(float4*)av1 = a1p[e4];
            #pragma unroll
            for (int j = 0; j < 4; j++) {
                unsigned long long aa0 = pack2(av0[j]);
                unsigned long long aa1 = pack2(av1[j]);
                const float* be = bp + (e4 * 4 + j) * NH;
                ulonglong2 blo = *(const ulonglong2*)be;          // cols tx*4..+3
                ulonglong2 bhi = *(const ulonglong2*)(be + 32);   // cols 32+tx*4..+3
                ffma2(acc[0][0], aa0, blo.x);
                ffma2(acc[0][1], aa0, blo.y);
                ffma2(acc[0][2], aa0, bhi.x);
                ffma2(acc[0][3], aa0, bhi.y);
                ffma2(acc[1][0], aa1, blo.x);
                ffma2(acc[1][1], aa1, blo.y);
                ffma2(acc[1][2], aa1, bhi.x);
                ffma2(acc[1][3], aa1, bhi.y);
            }
        }

        // epilogue: relu(acc + qA) . W1, reduce over the 8 tx lanes
        #pragma unroll
        for (int r = 0; r < 2; r++) {
            const int trow = ty * 2 + r;
            float s = 0.f;
            #pragma unroll
            for (int cp = 0; cp < 4; cp++) {
                float2 v = unpack2(acc[r][cp]);
                int h = (cp < 2) ? (tx * 4 + cp * 2) : (32 + tx * 4 + (cp - 2) * 2);
                float x0 = v.x + sqA[h];
                float x1 = v.y + sqA[h + 1];
                x0 = x0 > 0.f ? x0 : 0.f;
                x1 = x1 > 0.f ? x1 : 0.f;
                s += x0 * w1v[cp * 2] + x1 * w1v[cp * 2 + 1];
            }
            s += __shfl_down_sync(0xffffffffu, s, 4);
            s += __shfl_down_sync(0xffffffffu, s, 2);
            s += __shfl_down_sync(0xffffffffu, s, 1);
            if (tx == 0 && trow < rows)
                out[b * NT + t0 + trow] = s + b1v;
        }
    }
}

extern "C" void kernel_launch(void* const* d_in, const int* in_sizes, int n_in,
                              void* d_out, int out_size)
{
    const float* query = (const float*)d_in[0];
    const float* keys  = (const float*)d_in[1];
    const float* W0    = (const float*)d_in[2];
    const float* b0    = (const float*)d_in[3];
    const float* W1    = (const float*)d_in[4];
    const float* b1    = (const float*)d_in[5];
    float* out = (float*)d_out;

    const int smem_bytes = (NE * NH + 64 * APAD + NE + NH) * (int)sizeof(float);
    cudaFuncSetAttribute(lau_kernel, cudaFuncAttributeMaxDynamicSharedMemorySize,
                         smem_bytes);
    lau_kernel<<<NB, 256, smem_bytes>>>(query, keys, W0, b0, W1, b1, out);
}

// round 9
// speedup vs baseline: 2.2202x; 1.1363x over previous
#include <cuda_runtime.h>

// LocalActivationUnit: score[b,t] = relu([q,k,q-k,q*k] @ W0 + b0) @ W1 + b1
// Folded:  h = qA_b + k . C_b ; score = relu(h) @ W1 + b1.
//
// R8: 128 threads/CTA, 8x8 per-thread microtile (balances crossbar bytes vs FMA:
//     4*(r+c) == r*c at r=c=8). Odd smem stride S=129 + e-permuted key layout
//     gives fully conflict-free LDS/STS. 2 CTAs/SM.

#define NB 1024
#define NT 200
#define NE 128
#define NH 64
#define CHUNK 128
#define S 129   // sA row stride (floats), odd -> conflict-free scalar LDS/STS

__device__ __forceinline__ unsigned long long pack2(float x) {
    unsigned long long r;
    asm("mov.b64 %0, {%1, %1};" : "=l"(r) : "r"(__float_as_uint(x)));
    return r;
}
__device__ __forceinline__ void ffma2(unsigned long long &acc, unsigned long long a,
                                      unsigned long long b) {
    asm("fma.rn.f32x2 %0, %1, %2, %0;" : "+l"(acc) : "l"(a), "l"(b));
}
__device__ __forceinline__ float2 unpack2(unsigned long long v) {
    unsigned int lo, hi;
    asm("mov.b64 {%0, %1}, %2;" : "=r"(lo), "=r"(hi) : "l"(v));
    return make_float2(__uint_as_float(lo), __uint_as_float(hi));
}

__global__ void __launch_bounds__(128, 2)
lau_kernel(const float* __restrict__ query,
           const float* __restrict__ keys,
           const float* __restrict__ W0,
           const float* __restrict__ b0,
           const float* __restrict__ W1,
           const float* __restrict__ b1,
           float* __restrict__ out)
{
    extern __shared__ float smem[];
    float* sC  = smem;                 // [128][64] rows in permuted-p order
    float* sA  = smem + NE * NH;       // [CHUNK][S] keys, e-permuted within row
    float* sq  = sA + CHUNK * S;       // [128]
    float* sqA = sq + NE;              // [64]

    const int tid = threadIdx.x;
    const int b   = blockIdx.x;

    // ---- load q ----
    sq[tid] = query[b * NE + tid];
    __syncthreads();

    // ---- precompute C_b into smem (rows permuted: p -> e(p)=4*(p&31)+(p>>5)) ----
    const float* W0a = W0;
    const float* W0b = W0 + 128 * NH;
    const float* W0c = W0 + 256 * NH;
    const float* W0d = W0 + 384 * NH;
    #pragma unroll
    for (int j = 0; j < 16; j++) {
        int f = tid + 128 * j;          // float4 index, [0, 2048)
        int p = f >> 4;                 // 16 float4 per row
        int c = f & 15;
        int e = 4 * (p & 31) + (p >> 5);
        float qe = sq[e];
        float4 wb = *(const float4*)(W0b + e * NH + c * 4);
        float4 wc = *(const float4*)(W0c + e * NH + c * 4);
        float4 wd = *(const float4*)(W0d + e * NH + c * 4);
        float4 cv;
        cv.x = (wb.x - wc.x) + qe * wd.x;
        cv.y = (wb.y - wc.y) + qe * wd.y;
        cv.z = (wb.z - wc.z) + qe * wd.z;
        cv.w = (wb.w - wc.w) + qe * wd.w;
        *(float4*)&sC[f * 4] = cv;
    }
    // qA partials: 2 groups of 64 e-terms, scratch in sA
    {
        int h = tid & 63, g = tid >> 6;
        float ps = 0.f;
        int e0 = g * 64;
        #pragma unroll 4
        for (int e = e0; e < e0 + 64; e++)
            ps += sq[e] * (W0a[e * NH + h] + W0c[e * NH + h]);
        sA[g * 64 + h] = ps;
    }
    __syncthreads();
    if (tid < NH)
        sqA[tid] = b0[tid] + sA[tid] + sA[64 + tid];
    // (loop-start __syncthreads orders this vs. sA reuse)

    // ---- per-thread constants ----
    const int ty = tid >> 3;            // 0..15 -> 8 rows each
    const int tx = tid & 7;             // 0..7  -> cols {tx*4..+3, 32+tx*4..+3}
    float w1v[8];
    *(float4*)&w1v[0] = *(const float4*)(W1 + tx * 4);
    *(float4*)&w1v[4] = *(const float4*)(W1 + 32 + tx * 4);
    const float b1v = b1[0];
    const float* bp = sC + tx * 4;
    const unsigned gmask = 0xffu << ((tid & 31) & 24);  // 8-lane shfl group

    // ---- main loop over T in 128-row chunks ----
    for (int t0 = 0; t0 < NT; t0 += CHUNK) {
        const int rows = min(CHUNK, NT - t0);
        __syncthreads();   // previous GEMM done reading sA

        // loader: one warp per row; lane c4 scatters its 4 floats to words
        // {c4, 32+c4, 64+c4, 96+c4}  (bank = row + c4 mod 32: conflict-free)
        for (int f = tid; f < rows * 32; f += 128) {
            int row = f >> 5, c4 = f & 31;
            float4 v = *(const float4*)(keys + ((long)b * NT + t0 + row) * NE + c4 * 4);
            float* base = sA + row * S + c4;
            base[0]  = v.x;
            base[32] = v.y;
            base[64] = v.z;
            base[96] = v.w;
        }
        __syncthreads();

        if (ty * 8 < rows) {
            // GEMM: acc[8 rows][4 col-pairs], K=128 (permuted order, matches sC)
            unsigned long long acc[8][4];
            #pragma unroll
            for (int r = 0; r < 8; r++)
                #pragma unroll
                for (int c = 0; c < 4; c++) acc[r][c] = 0ull;

            const float* ap = sA + (ty * 8) * S;
            #pragma unroll 4
            for (int p = 0; p < NE; p++) {
                ulonglong2 blo = *(const ulonglong2*)(bp + p * NH);        // cols tx*4..+3
                ulonglong2 bhi = *(const ulonglong2*)(bp + p * NH + 32);   // cols 32+tx*4..+3
                #pragma unroll
                for (int r = 0; r < 8; r++) {
                    unsigned long long aa = pack2(ap[r * S + p]);
                    ffma2(acc[r][0], aa, blo.x);
                    ffma2(acc[r][1], aa, blo.y);
                    ffma2(acc[r][2], aa, bhi.x);
                    ffma2(acc[r][3], aa, bhi.y);
                }
            }

            // epilogue: relu(acc + qA) . W1, reduce over the 8 tx lanes
            #pragma unroll
            for (int r = 0; r < 8; r++) {
                const int trow = ty * 8 + r;
                float s = 0.f;
                #pragma unroll
                for (int cp = 0; cp < 4; cp++) {
                    float2 v = unpack2(acc[r][cp]);
                    int h = (cp < 2) ? (tx * 4 + cp * 2) : (32 + tx * 4 + (cp - 2) * 2);
                    float x0 = v.x + sqA[h];
                    float x1 = v.y + sqA[h + 1];
                    x0 = x0 > 0.f ? x0 : 0.f;
                    x1 = x1 > 0.f ? x1 : 0.f;
                    s += x0 * w1v[cp * 2] + x1 * w1v[cp * 2 + 1];
                }
                s += __shfl_down_sync(gmask, s, 4);
                s += __shfl_down_sync(gmask, s, 2);
                s += __shfl_down_sync(gmask, s, 1);
                if (tx == 0 && trow < rows)
                    out[b * NT + t0 + trow] = s + b1v;
            }
        }
    }
}

extern "C" void kernel_launch(void* const* d_in, const int* in_sizes, int n_in,
                              void* d_out, int out_size)
{
    const float* query = (const float*)d_in[0];
    const float* keys  = (const float*)d_in[1];
    const float* W0    = (const float*)d_in[2];
    const float* b0    = (const float*)d_in[3];
    const float* W1    = (const float*)d_in[4];
    const float* b1    = (const float*)d_in[5];
    float* out = (float*)d_out;

    const int smem_bytes = (NE * NH + CHUNK * S + NE + NH) * (int)sizeof(float);
    cudaFuncSetAttribute(lau_kernel, cudaFuncAttributeMaxDynamicSharedMemorySize,
                         smem_bytes);
    lau_kernel<<<NB, 128, smem_bytes>>>(query, keys, W0, b0, W1, b1, out);
}